// round 5
// baseline (speedup 1.0000x reference)
#include <cuda_runtime.h>
#include <cuda_fp16.h>
#include <math.h>

// ---------------------------------------------------------------------------
// CascadeGCN: 2-layer GCN, N=100000, c_in=5, hid=32, c_out=1.
// R5: fp16 t1 (half gather traffic, 2 edges/warp-iter) + atomic layer-2 scatter.
//   fill:      bkt[d][slot++] = s             (int atomics)
//   transform1:t1h = half((x@W1)*dinv)        (dinv = rsqrt(indeg+1))
//   gather1:   acc = t1[i] + sum t1[bkt] (fp32 accum);
//              h=relu(acc*dv+b1); t2 = agg2 = (h@W2)*dv
//   scatter2:  agg2[d] += t2[s]               (scalar f32 RED)
//   output:    out = sigmoid(agg2*dinv... already folded: agg2 holds z) -----
//              NOTE dinv[d] applied in output, b2 added there.
// Normalization algebra: msg = t[s] (already *dinv[s]); out[d] = dinv[d]*sum+b
// ---------------------------------------------------------------------------

#define NMAX 100000
#define CIN 5
#define HID 32
#define CAP 192   // max in-degree (Poisson(25): P(>=192) ~ e^-224)

__device__ __align__(16) int    g_cnt [NMAX];        // in-degree (excl. self)
__device__ __align__(16) float  g_dinv[NMAX];
__device__ __align__(16) int    g_bkt [NMAX * CAP];  // incoming src ids
__device__ __align__(16) __half g_t1h [NMAX * HID];  // half((x@W1)*dinv[src])
__device__ __align__(16) float  g_t2  [NMAX];        // (h1@W2)*dinv[src]
__device__ __align__(16) float  g_agg2[NMAX];        // layer-2 accumulator

// --- build buckets ----------------------------------------------------------
__global__ void k_fill(const int* __restrict__ src,
                       const int* __restrict__ dst, int e) {
    int i = blockIdx.x * blockDim.x + threadIdx.x;
    if (i >= e) return;
    int d = __ldg(&dst[i]);
    int s = __ldg(&src[i]);
    int slot = atomicAdd(&g_cnt[d], 1);
    if (slot < CAP) g_bkt[d * CAP + slot] = s;
}

// --- t1h = half((x @ W1) * dinv)  (warp per node, lane = feature) ----------
__global__ void k_transform1(const float* __restrict__ x,
                             const float* __restrict__ W1, int n) {
    int t = blockIdx.x * blockDim.x + threadIdx.x;
    int i = t >> 5;
    int k = t & 31;
    if (i >= n) return;
    float dv = rsqrtf((float)(g_cnt[i] + 1));   // +1 self loop
    if (k == 0) g_dinv[i] = dv;
    float acc = 0.f;
#pragma unroll
    for (int j = 0; j < CIN; j++)
        acc += __ldg(&x[i * CIN + j]) * __ldg(&W1[j * HID + k]);
    g_t1h[i * HID + k] = __float2half_rn(acc * dv);
}

// --- layer1 gather (fp16 rows, 2 edges per warp-iter) + fused layer2 -------
// lane = (half, kp): half=lane>>4 picks edge parity, kp=lane&15 picks the
// half2 feature pair {2kp, 2kp+1}. fp32 accumulation.
__global__ void k_gather1(const float* __restrict__ b1,
                          const float* __restrict__ W2, int n) {
    int t = blockIdx.x * blockDim.x + threadIdx.x;
    int i = t >> 5;
    int lane = t & 31;
    int kp = lane & 15;
    int hf = lane >> 4;
    if (i >= n) return;
    int deg = g_cnt[i];
    if (deg > CAP) deg = CAP;
    const int* row = &g_bkt[i * CAP];

    float ax = 0.f, ay = 0.f;
    if (hf == 0) {  // self loop once
        __half2 v = __ldg(reinterpret_cast<const __half2*>(&g_t1h[i * HID]) + kp);
        float2 f = __half22float2(v);
        ax = f.x; ay = f.y;
    }
    for (int j = hf; j < deg; j += 2) {
        int s = __ldg(&row[j]);
        __half2 v = __ldg(reinterpret_cast<const __half2*>(&g_t1h[s * HID]) + kp);
        float2 f = __half22float2(v);
        ax += f.x; ay += f.y;
    }
    // fold hi half-warp into lo
    ax += __shfl_down_sync(0xffffffffu, ax, 16);
    ay += __shfl_down_sync(0xffffffffu, ay, 16);

    float dv = g_dinv[i];
    float hx = fmaxf(ax * dv + __ldg(&b1[2 * kp]),     0.f);
    float hy = fmaxf(ay * dv + __ldg(&b1[2 * kp + 1]), 0.f);
    float p  = hx * __ldg(&W2[2 * kp]) + hy * __ldg(&W2[2 * kp + 1]);
#pragma unroll
    for (int o = 8; o > 0; o >>= 1)
        p += __shfl_xor_sync(0xffffffffu, p, o);
    if (lane == 0) {
        float v = p * dv;
        g_t2[i]   = v;
        g_agg2[i] = v;  // self loop
    }
}

// --- layer 2 scatter: agg2[d] += t2[s]  (thread per edge, scalar RED) ------
__global__ void k_scatter2(const int* __restrict__ src,
                           const int* __restrict__ dst, int e) {
    int i = blockIdx.x * blockDim.x + threadIdx.x;
    if (i >= e) return;
    atomicAdd(&g_agg2[__ldg(&dst[i])], __ldg(&g_t2[__ldg(&src[i])]));
}

// --- output: sigmoid(agg2*dinv + b2) ----------------------------------------
__global__ void k_output(float* __restrict__ out,
                         const float* __restrict__ b2, int n) {
    int i = blockIdx.x * blockDim.x + threadIdx.x;
    if (i >= n) return;
    float z = g_agg2[i] * g_dinv[i] + __ldg(&b2[0]);
    out[i] = 1.0f / (1.0f + expf(-z));
}

extern "C" void kernel_launch(void* const* d_in, const int* in_sizes, int n_in,
                              void* d_out, int out_size) {
    const float* x  = (const float*)d_in[0];
    const int*   ei = (const int*)d_in[1];   // int32 (JAX x64 disabled)
    const float* W1 = (const float*)d_in[2];
    const float* b1 = (const float*)d_in[3];
    const float* W2 = (const float*)d_in[4];
    const float* b2 = (const float*)d_in[5];
    float* out = (float*)d_out;

    int n = in_sizes[0] / CIN;
    int e = in_sizes[1] / 2;
    const int* src = ei;
    const int* dst = ei + e;

    void* cnt_ptr = nullptr;
    cudaGetSymbolAddress(&cnt_ptr, g_cnt);
    cudaMemsetAsync(cnt_ptr, 0, (size_t)n * sizeof(int), 0);

    const int B = 256;
    int gridN = (n + B - 1) / B;
    int gridE = (e + B - 1) / B;
    long long tn = (long long)n * 32;
    int gridN32 = (int)((tn + B - 1) / B);

    k_fill      <<<gridE,   B>>>(src, dst, e);
    k_transform1<<<gridN32, B>>>(x, W1, n);
    k_gather1   <<<gridN32, B>>>(b1, W2, n);
    k_scatter2  <<<gridE,   B>>>(src, dst, e);
    k_output    <<<gridN,   B>>>(out, b2, n);
}

// round 6
// speedup vs baseline: 1.0930x; 1.0930x over previous
#include <cuda_runtime.h>
#include <math.h>

// ---------------------------------------------------------------------------
// CascadeGCN: 2-layer GCN, N=100000, c_in=5, hid=32, c_out=1.
// R6: aggregate-then-transform. Layer-1 aggregation runs on RAW 5-wide
//     features (padded to 32B rows) -> one sector per edge gather.
//   fill:    bkt[d][slot++] = s                (int atomics)
//   prep:    xs[i] = x[i]*dinv[i]  (8-float row, 32B)
//   gather1: aggx = xs[i] + sum xs[bkt];  h = relu(dv*(aggx@W1)+b1);
//            t2 = agg2 = dv*(h@W2)        (all fused, per node)
//   scatter2:agg2[d] += t2[s]   (4-edge ILP, scalar RED)
//   output:  out = sigmoid(agg2*dinv + b2)
// ---------------------------------------------------------------------------

#define NMAX 100000
#define CIN 5
#define HID 32
#define CAP 192   // max in-degree (Poisson(25): P(>=192) ~ e^-224)

__device__ __align__(16) int   g_cnt [NMAX];        // in-degree (excl. self)
__device__ __align__(16) float g_dinv[NMAX];
__device__ __align__(16) int   g_bkt [NMAX * CAP];  // incoming src ids
__device__ __align__(16) float g_xs  [NMAX * 8];    // x*dinv, padded to 32B
__device__ __align__(16) float g_t2  [NMAX];        // dv*(h1@W2)
__device__ __align__(16) float g_agg2[NMAX];

// --- build buckets ----------------------------------------------------------
__global__ void k_fill(const int* __restrict__ src,
                       const int* __restrict__ dst, int e) {
    int i = blockIdx.x * blockDim.x + threadIdx.x;
    if (i >= e) return;
    int d = __ldg(&dst[i]);
    int s = __ldg(&src[i]);
    int slot = atomicAdd(&g_cnt[d], 1);
    if (slot < CAP) g_bkt[d * CAP + slot] = s;
}

// --- xs = x * dinv, padded to 8 floats (thread per node) -------------------
__global__ void k_prep(const float* __restrict__ x, int n) {
    int i = blockIdx.x * blockDim.x + threadIdx.x;
    if (i >= n) return;
    float dv = rsqrtf((float)(g_cnt[i] + 1));   // +1 self loop
    g_dinv[i] = dv;
    float4 a;
    a.x = __ldg(&x[i * CIN + 0]) * dv;
    a.y = __ldg(&x[i * CIN + 1]) * dv;
    a.z = __ldg(&x[i * CIN + 2]) * dv;
    a.w = __ldg(&x[i * CIN + 3]) * dv;
    float4 b;
    b.x = __ldg(&x[i * CIN + 4]) * dv;
    b.y = 0.f; b.z = 0.f; b.w = 0.f;
    reinterpret_cast<float4*>(&g_xs[i * 8])[0] = a;
    reinterpret_cast<float4*>(&g_xs[i * 8])[1] = b;
}

// --- fused: 5-wide gather -> W1 -> relu -> W2 -> t2/agg2 (warp per node) ---
// lane = 8*sub + f: sub in [0,4) strides over edges, f indexes the 8-float row.
__global__ void k_gather1(const float* __restrict__ W1,
                          const float* __restrict__ b1,
                          const float* __restrict__ W2, int n) {
    int t = blockIdx.x * blockDim.x + threadIdx.x;
    int i = t >> 5;
    int lane = t & 31;
    if (i >= n) return;
    int sub = lane >> 3;
    int f = lane & 7;
    int deg = g_cnt[i];
    if (deg > CAP) deg = CAP;
    const int* row = &g_bkt[i * CAP];

    float acc = (sub == 0) ? g_xs[i * 8 + f] : 0.f;   // self loop
    for (int j = sub; j < deg; j += 4) {
        int s = __ldg(&row[j]);                        // broadcast across 8 lanes
        acc += __ldg(&g_xs[s * 8 + f]);                // one 32B sector per edge
    }
    acc += __shfl_down_sync(0xffffffffu, acc, 16);
    acc += __shfl_down_sync(0xffffffffu, acc, 8);
    // lanes 0..4 now hold aggx[0..4]; broadcast to all lanes
    float a0 = __shfl_sync(0xffffffffu, acc, 0);
    float a1 = __shfl_sync(0xffffffffu, acc, 1);
    float a2 = __shfl_sync(0xffffffffu, acc, 2);
    float a3 = __shfl_sync(0xffffffffu, acc, 3);
    float a4 = __shfl_sync(0xffffffffu, acc, 4);

    float dv = g_dinv[i];
    int k = lane;  // hidden feature
    float z = a0 * __ldg(&W1[0 * HID + k]) + a1 * __ldg(&W1[1 * HID + k])
            + a2 * __ldg(&W1[2 * HID + k]) + a3 * __ldg(&W1[3 * HID + k])
            + a4 * __ldg(&W1[4 * HID + k]);
    float h = fmaxf(z * dv + __ldg(&b1[k]), 0.f);
    float p = h * __ldg(&W2[k]);
#pragma unroll
    for (int o = 16; o > 0; o >>= 1)
        p += __shfl_xor_sync(0xffffffffu, p, o);
    if (lane == 0) {
        float v = p * dv;
        g_t2[i]   = v;
        g_agg2[i] = v;  // self loop
    }
}

// --- layer 2 scatter with 4-edge ILP ----------------------------------------
__global__ void k_scatter2(const int* __restrict__ src,
                           const int* __restrict__ dst, int e) {
    int tid = blockIdx.x * blockDim.x + threadIdx.x;
    int gsz = gridDim.x * blockDim.x;
    int i0 = tid, i1 = tid + gsz, i2 = tid + 2 * gsz, i3 = tid + 3 * gsz;
    int s0 = 0, s1 = 0, s2 = 0, s3 = 0;
    int d0 = 0, d1 = 0, d2 = 0, d3 = 0;
    if (i0 < e) { s0 = __ldg(&src[i0]); d0 = __ldg(&dst[i0]); }
    if (i1 < e) { s1 = __ldg(&src[i1]); d1 = __ldg(&dst[i1]); }
    if (i2 < e) { s2 = __ldg(&src[i2]); d2 = __ldg(&dst[i2]); }
    if (i3 < e) { s3 = __ldg(&src[i3]); d3 = __ldg(&dst[i3]); }
    float v0 = 0.f, v1 = 0.f, v2 = 0.f, v3 = 0.f;
    if (i0 < e) v0 = __ldg(&g_t2[s0]);   // 4 independent random loads in flight
    if (i1 < e) v1 = __ldg(&g_t2[s1]);
    if (i2 < e) v2 = __ldg(&g_t2[s2]);
    if (i3 < e) v3 = __ldg(&g_t2[s3]);
    if (i0 < e) atomicAdd(&g_agg2[d0], v0);
    if (i1 < e) atomicAdd(&g_agg2[d1], v1);
    if (i2 < e) atomicAdd(&g_agg2[d2], v2);
    if (i3 < e) atomicAdd(&g_agg2[d3], v3);
}

// --- output: sigmoid(agg2*dinv + b2) ----------------------------------------
__global__ void k_output(float* __restrict__ out,
                         const float* __restrict__ b2, int n) {
    int i = blockIdx.x * blockDim.x + threadIdx.x;
    if (i >= n) return;
    float z = g_agg2[i] * g_dinv[i] + __ldg(&b2[0]);
    out[i] = 1.0f / (1.0f + expf(-z));
}

extern "C" void kernel_launch(void* const* d_in, const int* in_sizes, int n_in,
                              void* d_out, int out_size) {
    const float* x  = (const float*)d_in[0];
    const int*   ei = (const int*)d_in[1];   // int32 (JAX x64 disabled)
    const float* W1 = (const float*)d_in[2];
    const float* b1 = (const float*)d_in[3];
    const float* W2 = (const float*)d_in[4];
    const float* b2 = (const float*)d_in[5];
    float* out = (float*)d_out;

    int n = in_sizes[0] / CIN;
    int e = in_sizes[1] / 2;
    const int* src = ei;
    const int* dst = ei + e;

    void* cnt_ptr = nullptr;
    cudaGetSymbolAddress(&cnt_ptr, g_cnt);
    cudaMemsetAsync(cnt_ptr, 0, (size_t)n * sizeof(int), 0);

    const int B = 256;
    int gridN  = (n + B - 1) / B;
    int gridE  = (e + B - 1) / B;
    int gridE4 = (e + B * 4 - 1) / (B * 4);
    long long tn = (long long)n * 32;
    int gridN32 = (int)((tn + B - 1) / B);

    k_fill    <<<gridE,   B>>>(src, dst, e);
    k_prep    <<<gridN,   B>>>(x, n);
    k_gather1 <<<gridN32, B>>>(W1, b1, W2, n);
    k_scatter2<<<gridE4,  B>>>(src, dst, e);
    k_output  <<<gridN,   B>>>(out, b2, n);
}

// round 7
// speedup vs baseline: 1.2349x; 1.1299x over previous
#include <cuda_runtime.h>
#include <math.h>

// ---------------------------------------------------------------------------
// CascadeGCN: 2-layer GCN, N=100000, c_in=5, hid=32, c_out=1.
// R7: all-gather pipeline, layer-2 gather fused with sigmoid/output.
//   fill:    bkt[d][slot++] = s              (int atomics)
//   prep:    xs[i] = x[i]*dinv[i]            (8-float row, 32B sector)
//   gather1: aggx = xs[i]+sum xs[bkt]; h=relu(dv*(aggx@W1)+b1);
//            t2[i] = dv*(h@W2)
//   gather2: z = t2[i]+sum t2[bkt]; out[i]=sigmoid(z*dv+b2)  (4 nodes/warp)
// ---------------------------------------------------------------------------

#define NMAX 100000
#define CIN 5
#define HID 32
#define CAP 192   // max in-degree (Poisson(25): P(>=192) ~ e^-224)

__device__ __align__(16) int   g_cnt [NMAX];        // in-degree (excl. self)
__device__ __align__(16) float g_dinv[NMAX];
__device__ __align__(16) int   g_bkt [NMAX * CAP];  // incoming src ids
__device__ __align__(16) float g_xs  [NMAX * 8];    // x*dinv, padded to 32B
__device__ __align__(16) float g_t2  [NMAX];        // dv*(h1@W2)

// --- build buckets ----------------------------------------------------------
__global__ void k_fill(const int* __restrict__ src,
                       const int* __restrict__ dst, int e) {
    int i = blockIdx.x * blockDim.x + threadIdx.x;
    if (i >= e) return;
    int d = __ldg(&dst[i]);
    int s = __ldg(&src[i]);
    int slot = atomicAdd(&g_cnt[d], 1);
    if (slot < CAP) g_bkt[d * CAP + slot] = s;
}

// --- xs = x * dinv, padded to 8 floats (thread per node) -------------------
__global__ void k_prep(const float* __restrict__ x, int n) {
    int i = blockIdx.x * blockDim.x + threadIdx.x;
    if (i >= n) return;
    float dv = rsqrtf((float)(g_cnt[i] + 1));   // +1 self loop
    g_dinv[i] = dv;
    float4 a;
    a.x = __ldg(&x[i * CIN + 0]) * dv;
    a.y = __ldg(&x[i * CIN + 1]) * dv;
    a.z = __ldg(&x[i * CIN + 2]) * dv;
    a.w = __ldg(&x[i * CIN + 3]) * dv;
    float4 b;
    b.x = __ldg(&x[i * CIN + 4]) * dv;
    b.y = 0.f; b.z = 0.f; b.w = 0.f;
    reinterpret_cast<float4*>(&g_xs[i * 8])[0] = a;
    reinterpret_cast<float4*>(&g_xs[i * 8])[1] = b;
}

// --- fused: 5-wide gather -> W1 -> relu -> W2 -> t2 (warp per node) --------
// lane = 8*sub + f: sub strides over edges (x4), f indexes the 8-float row.
__global__ void k_gather1(const float* __restrict__ W1,
                          const float* __restrict__ b1,
                          const float* __restrict__ W2, int n) {
    int t = blockIdx.x * blockDim.x + threadIdx.x;
    int i = t >> 5;
    int lane = t & 31;
    if (i >= n) return;
    int sub = lane >> 3;
    int f = lane & 7;
    int deg = g_cnt[i];
    if (deg > CAP) deg = CAP;
    const int* row = &g_bkt[i * CAP];

    float acc0 = (sub == 0) ? g_xs[i * 8 + f] : 0.f;   // self loop
    float acc1 = 0.f;
    int j = sub;
    for (; j + 4 < deg; j += 8) {           // 2-way unroll: MLP=2
        int s0 = __ldg(&row[j]);
        int s1 = __ldg(&row[j + 4]);
        acc0 += __ldg(&g_xs[s0 * 8 + f]);
        acc1 += __ldg(&g_xs[s1 * 8 + f]);
    }
    if (j < deg)
        acc0 += __ldg(&g_xs[__ldg(&row[j]) * 8 + f]);
    float acc = acc0 + acc1;
    acc += __shfl_down_sync(0xffffffffu, acc, 16);
    acc += __shfl_down_sync(0xffffffffu, acc, 8);
    float a0 = __shfl_sync(0xffffffffu, acc, 0);
    float a1 = __shfl_sync(0xffffffffu, acc, 1);
    float a2 = __shfl_sync(0xffffffffu, acc, 2);
    float a3 = __shfl_sync(0xffffffffu, acc, 3);
    float a4 = __shfl_sync(0xffffffffu, acc, 4);

    float dv = g_dinv[i];
    int k = lane;
    float z = a0 * __ldg(&W1[0 * HID + k]) + a1 * __ldg(&W1[1 * HID + k])
            + a2 * __ldg(&W1[2 * HID + k]) + a3 * __ldg(&W1[3 * HID + k])
            + a4 * __ldg(&W1[4 * HID + k]);
    float h = fmaxf(z * dv + __ldg(&b1[k]), 0.f);
    float p = h * __ldg(&W2[k]);
#pragma unroll
    for (int o = 16; o > 0; o >>= 1)
        p += __shfl_xor_sync(0xffffffffu, p, o);
    if (lane == 0) g_t2[i] = p * dv;
}

// --- layer-2 gather + sigmoid + output (4 nodes per warp, 8 lanes each) ----
__global__ void k_gather2(float* __restrict__ out,
                          const float* __restrict__ b2, int n) {
    int t = blockIdx.x * blockDim.x + threadIdx.x;
    int i = t >> 3;                 // node (8 lanes per node)
    int r = t & 7;                  // lane within group
    if (i >= n) return;
    int deg = g_cnt[i];
    if (deg > CAP) deg = CAP;
    const int* row = &g_bkt[i * CAP];

    float z0 = (r == 0) ? g_t2[i] : 0.f;   // self loop
    float z1 = 0.f;
    int j = r;
    for (; j + 8 < deg; j += 16) {         // 2-way unroll: MLP=2
        int s0 = __ldg(&row[j]);
        int s1 = __ldg(&row[j + 8]);
        z0 += __ldg(&g_t2[s0]);
        z1 += __ldg(&g_t2[s1]);
    }
    if (j < deg)
        z0 += __ldg(&g_t2[__ldg(&row[j])]);
    float z = z0 + z1;
    z += __shfl_xor_sync(0xffffffffu, z, 4);
    z += __shfl_xor_sync(0xffffffffu, z, 2);
    z += __shfl_xor_sync(0xffffffffu, z, 1);
    if (r == 0) {
        float v = z * g_dinv[i] + __ldg(&b2[0]);
        out[i] = 1.0f / (1.0f + expf(-v));
    }
}

extern "C" void kernel_launch(void* const* d_in, const int* in_sizes, int n_in,
                              void* d_out, int out_size) {
    const float* x  = (const float*)d_in[0];
    const int*   ei = (const int*)d_in[1];   // int32 (JAX x64 disabled)
    const float* W1 = (const float*)d_in[2];
    const float* b1 = (const float*)d_in[3];
    const float* W2 = (const float*)d_in[4];
    const float* b2 = (const float*)d_in[5];
    float* out = (float*)d_out;

    int n = in_sizes[0] / CIN;
    int e = in_sizes[1] / 2;
    const int* src = ei;
    const int* dst = ei + e;

    void* cnt_ptr = nullptr;
    cudaGetSymbolAddress(&cnt_ptr, g_cnt);
    cudaMemsetAsync(cnt_ptr, 0, (size_t)n * sizeof(int), 0);

    const int B = 256;
    int gridN  = (n + B - 1) / B;
    int gridE  = (e + B - 1) / B;
    long long tn32 = (long long)n * 32;
    long long tn8  = (long long)n * 8;
    int gridN32 = (int)((tn32 + B - 1) / B);
    int gridN8  = (int)((tn8  + B - 1) / B);

    k_fill   <<<gridE,   B>>>(src, dst, e);
    k_prep   <<<gridN,   B>>>(x, n);
    k_gather1<<<gridN32, B>>>(W1, b1, W2, n);
    k_gather2<<<gridN8,  B>>>(out, b2, n);
}

// round 8
// speedup vs baseline: 1.2461x; 1.0090x over previous
#include <cuda_runtime.h>
#include <math.h>

// ---------------------------------------------------------------------------
// CascadeGCN: 2-layer GCN, N=100000, c_in=5, hid=32, c_out=1.
// R8: MLP=4 on all random gathers (batched predicated loads).
//   fill:    bkt[d][slot++] = s              (int atomics)
//   prep:    xs[i] = x[i]*dinv[i]            (8-float row, 32B sector)
//   gather1: aggx = xs[i]+sum xs[bkt]; h=relu(dv*(aggx@W1)+b1); t2=dv*(h@W2)
//   gather2: z = t2[i]+sum t2[bkt]; out[i]=sigmoid(z*dv+b2)  (4 nodes/warp)
// ---------------------------------------------------------------------------

#define NMAX 100000
#define CIN 5
#define HID 32
#define CAP 192   // max in-degree (Poisson(25): P(>=192) ~ e^-224)

__device__ __align__(16) int   g_cnt [NMAX];        // in-degree (excl. self)
__device__ __align__(16) float g_dinv[NMAX];
__device__ __align__(16) int   g_bkt [NMAX * CAP];  // incoming src ids
__device__ __align__(16) float g_xs  [NMAX * 8];    // x*dinv, padded to 32B
__device__ __align__(16) float g_t2  [NMAX];        // dv*(h1@W2)

// --- build buckets ----------------------------------------------------------
__global__ void k_fill(const int* __restrict__ src,
                       const int* __restrict__ dst, int e) {
    int i = blockIdx.x * blockDim.x + threadIdx.x;
    if (i >= e) return;
    int d = __ldg(&dst[i]);
    int s = __ldg(&src[i]);
    int slot = atomicAdd(&g_cnt[d], 1);
    if (slot < CAP) g_bkt[d * CAP + slot] = s;
}

// --- xs = x * dinv, padded to 8 floats (thread per node) -------------------
__global__ void k_prep(const float* __restrict__ x, int n) {
    int i = blockIdx.x * blockDim.x + threadIdx.x;
    if (i >= n) return;
    float dv = rsqrtf((float)(g_cnt[i] + 1));   // +1 self loop
    g_dinv[i] = dv;
    float4 a;
    a.x = __ldg(&x[i * CIN + 0]) * dv;
    a.y = __ldg(&x[i * CIN + 1]) * dv;
    a.z = __ldg(&x[i * CIN + 2]) * dv;
    a.w = __ldg(&x[i * CIN + 3]) * dv;
    float4 b;
    b.x = __ldg(&x[i * CIN + 4]) * dv;
    b.y = 0.f; b.z = 0.f; b.w = 0.f;
    reinterpret_cast<float4*>(&g_xs[i * 8])[0] = a;
    reinterpret_cast<float4*>(&g_xs[i * 8])[1] = b;
}

// --- fused: 5-wide gather -> W1 -> relu -> W2 -> t2 (warp per node) --------
// lane = 8*sub + f: sub strides over edges (x4), f indexes the 8-float row.
// 4-way unrolled neighbor loop -> 4 independent sector loads in flight.
__global__ void k_gather1(const float* __restrict__ W1,
                          const float* __restrict__ b1,
                          const float* __restrict__ W2, int n) {
    int t = blockIdx.x * blockDim.x + threadIdx.x;
    int i = t >> 5;
    int lane = t & 31;
    if (i >= n) return;
    int sub = lane >> 3;
    int f = lane & 7;
    int deg = g_cnt[i];
    if (deg > CAP) deg = CAP;
    const int* row = &g_bkt[i * CAP];

    float acc0 = (sub == 0) ? g_xs[i * 8 + f] : 0.f;   // self loop
    float acc1 = 0.f, acc2 = 0.f, acc3 = 0.f;
    int j = sub;
    for (; j + 12 < deg; j += 16) {         // 4-way unroll: MLP=4
        int s0 = __ldg(&row[j]);
        int s1 = __ldg(&row[j + 4]);
        int s2 = __ldg(&row[j + 8]);
        int s3 = __ldg(&row[j + 12]);
        acc0 += __ldg(&g_xs[s0 * 8 + f]);
        acc1 += __ldg(&g_xs[s1 * 8 + f]);
        acc2 += __ldg(&g_xs[s2 * 8 + f]);
        acc3 += __ldg(&g_xs[s3 * 8 + f]);
    }
    for (; j < deg; j += 4)
        acc0 += __ldg(&g_xs[__ldg(&row[j]) * 8 + f]);
    float acc = (acc0 + acc1) + (acc2 + acc3);
    acc += __shfl_down_sync(0xffffffffu, acc, 16);
    acc += __shfl_down_sync(0xffffffffu, acc, 8);
    float a0 = __shfl_sync(0xffffffffu, acc, 0);
    float a1 = __shfl_sync(0xffffffffu, acc, 1);
    float a2 = __shfl_sync(0xffffffffu, acc, 2);
    float a3 = __shfl_sync(0xffffffffu, acc, 3);
    float a4 = __shfl_sync(0xffffffffu, acc, 4);

    float dv = g_dinv[i];
    int k = lane;
    float z = a0 * __ldg(&W1[0 * HID + k]) + a1 * __ldg(&W1[1 * HID + k])
            + a2 * __ldg(&W1[2 * HID + k]) + a3 * __ldg(&W1[3 * HID + k])
            + a4 * __ldg(&W1[4 * HID + k]);
    float h = fmaxf(z * dv + __ldg(&b1[k]), 0.f);
    float p = h * __ldg(&W2[k]);
#pragma unroll
    for (int o = 16; o > 0; o >>= 1)
        p += __shfl_xor_sync(0xffffffffu, p, o);
    if (lane == 0) g_t2[i] = p * dv;
}

// --- layer-2 gather + sigmoid + output (4 nodes/warp, 8 lanes each) --------
// Batched: issue up to 4 predicated index loads, then 4 independent t2 loads.
__global__ void k_gather2(float* __restrict__ out,
                          const float* __restrict__ b2, int n) {
    int t = blockIdx.x * blockDim.x + threadIdx.x;
    int i = t >> 3;                 // node (8 lanes per node)
    int r = t & 7;                  // lane within group
    if (i >= n) return;
    int deg = g_cnt[i];
    if (deg > CAP) deg = CAP;
    const int* row = &g_bkt[i * CAP];

    float z = (r == 0) ? g_t2[i] : 0.f;    // self loop
    int j = r;
    while (j < deg) {
        // batch up to 4 row elements for this lane: j, j+8, j+16, j+24
        int s0 = __ldg(&row[j]);
        int s1 = (j +  8 < deg) ? __ldg(&row[j +  8]) : -1;
        int s2 = (j + 16 < deg) ? __ldg(&row[j + 16]) : -1;
        int s3 = (j + 24 < deg) ? __ldg(&row[j + 24]) : -1;
        float v0 = __ldg(&g_t2[s0]);               // 4 loads in flight
        float v1 = (s1 >= 0) ? __ldg(&g_t2[s1]) : 0.f;
        float v2 = (s2 >= 0) ? __ldg(&g_t2[s2]) : 0.f;
        float v3 = (s3 >= 0) ? __ldg(&g_t2[s3]) : 0.f;
        z += (v0 + v1) + (v2 + v3);
        j += 32;
    }
    z += __shfl_xor_sync(0xffffffffu, z, 4);
    z += __shfl_xor_sync(0xffffffffu, z, 2);
    z += __shfl_xor_sync(0xffffffffu, z, 1);
    if (r == 0) {
        float v = z * g_dinv[i] + __ldg(&b2[0]);
        out[i] = 1.0f / (1.0f + expf(-v));
    }
}

extern "C" void kernel_launch(void* const* d_in, const int* in_sizes, int n_in,
                              void* d_out, int out_size) {
    const float* x  = (const float*)d_in[0];
    const int*   ei = (const int*)d_in[1];   // int32 (JAX x64 disabled)
    const float* W1 = (const float*)d_in[2];
    const float* b1 = (const float*)d_in[3];
    const float* W2 = (const float*)d_in[4];
    const float* b2 = (const float*)d_in[5];
    float* out = (float*)d_out;

    int n = in_sizes[0] / CIN;
    int e = in_sizes[1] / 2;
    const int* src = ei;
    const int* dst = ei + e;

    void* cnt_ptr = nullptr;
    cudaGetSymbolAddress(&cnt_ptr, g_cnt);
    cudaMemsetAsync(cnt_ptr, 0, (size_t)n * sizeof(int), 0);

    const int B = 256;
    int gridN = (n + B - 1) / B;
    int gridE = (e + B - 1) / B;
    long long tn32 = (long long)n * 32;
    long long tn8  = (long long)n * 8;
    int gridN32 = (int)((tn32 + B - 1) / B);
    int gridN8  = (int)((tn8  + B - 1) / B);

    k_fill   <<<gridE,   B>>>(src, dst, e);
    k_prep   <<<gridN,   B>>>(x, n);
    k_gather1<<<gridN32, B>>>(W1, b1, W2, n);
    k_gather2<<<gridN8,  B>>>(out, b2, n);
}

// round 9
// speedup vs baseline: 1.3397x; 1.0751x over previous
#include <cuda_runtime.h>
#include <math.h>

// ---------------------------------------------------------------------------
// CascadeGCN: 2-layer GCN, N=100000, c_in=5, hid=32, c_out=1.
// R9: high-MLP gathers. gather1: 32-edge windows, shfl-distributed indices,
//     8 value loads in flight per lane. gather2: 4 lanes/node, int4 index
//     loads, 8 value loads in flight per lane.
// ---------------------------------------------------------------------------

#define NMAX 100000
#define CIN 5
#define HID 32
#define CAP 192   // max in-degree (Poisson(25): P(>=192) ~ e^-224)

__device__ __align__(16) int   g_cnt [NMAX];            // in-degree (excl. self)
__device__ __align__(16) float g_dinv[NMAX];
__device__ __align__(16) int   g_bkt [NMAX * CAP + 32]; // +32 pad for int4 reads
__device__ __align__(16) float g_xs  [NMAX * 8];        // x*dinv, 32B rows
__device__ __align__(16) float g_t2  [NMAX];            // dv*(h1@W2)

// --- build buckets ----------------------------------------------------------
__global__ void k_fill(const int* __restrict__ src,
                       const int* __restrict__ dst, int e) {
    int i = blockIdx.x * blockDim.x + threadIdx.x;
    if (i >= e) return;
    int d = __ldg(&dst[i]);
    int s = __ldg(&src[i]);
    int slot = atomicAdd(&g_cnt[d], 1);
    if (slot < CAP) g_bkt[d * CAP + slot] = s;
}

// --- xs = x * dinv, padded to 8 floats (thread per node) -------------------
__global__ void k_prep(const float* __restrict__ x, int n) {
    int i = blockIdx.x * blockDim.x + threadIdx.x;
    if (i >= n) return;
    float dv = rsqrtf((float)(g_cnt[i] + 1));   // +1 self loop
    g_dinv[i] = dv;
    float4 a;
    a.x = __ldg(&x[i * CIN + 0]) * dv;
    a.y = __ldg(&x[i * CIN + 1]) * dv;
    a.z = __ldg(&x[i * CIN + 2]) * dv;
    a.w = __ldg(&x[i * CIN + 3]) * dv;
    float4 b;
    b.x = __ldg(&x[i * CIN + 4]) * dv;
    b.y = 0.f; b.z = 0.f; b.w = 0.f;
    reinterpret_cast<float4*>(&g_xs[i * 8])[0] = a;
    reinterpret_cast<float4*>(&g_xs[i * 8])[1] = b;
}

// --- fused: 5-wide gather -> W1 -> relu -> W2 -> t2 (warp per node) --------
// 32-edge windows. Octet o, lane f. Index load coalesced across the warp;
// each octet walks its 8 indices via shfl -> 8 value loads in flight.
__global__ void __launch_bounds__(256)
k_gather1(const float* __restrict__ W1, const float* __restrict__ b1,
          const float* __restrict__ W2, int n) {
    int t = blockIdx.x * blockDim.x + threadIdx.x;
    int i = t >> 5;
    int lane = t & 31;
    if (i >= n) return;
    int o = lane >> 3;
    int f = lane & 7;
    int deg = g_cnt[i];
    if (deg > CAP) deg = CAP;
    const int* row = &g_bkt[i * CAP];

    float acc = (o == 0) ? g_xs[i * 8 + f] : 0.f;   // self loop
    int ob = o * 8;
    for (int base = 0; base < deg; base += 32) {
        int j = base + ob + f;
        int idx = (j < deg) ? __ldg(&row[j]) : -1;   // 1 coalesced wavefront
        int s0 = __shfl_sync(0xffffffffu, idx, ob + 0);
        int s1 = __shfl_sync(0xffffffffu, idx, ob + 1);
        int s2 = __shfl_sync(0xffffffffu, idx, ob + 2);
        int s3 = __shfl_sync(0xffffffffu, idx, ob + 3);
        int s4 = __shfl_sync(0xffffffffu, idx, ob + 4);
        int s5 = __shfl_sync(0xffffffffu, idx, ob + 5);
        int s6 = __shfl_sync(0xffffffffu, idx, ob + 6);
        int s7 = __shfl_sync(0xffffffffu, idx, ob + 7);
        float v0 = (s0 >= 0) ? __ldg(&g_xs[s0 * 8 + f]) : 0.f;  // 8 in flight
        float v1 = (s1 >= 0) ? __ldg(&g_xs[s1 * 8 + f]) : 0.f;
        float v2 = (s2 >= 0) ? __ldg(&g_xs[s2 * 8 + f]) : 0.f;
        float v3 = (s3 >= 0) ? __ldg(&g_xs[s3 * 8 + f]) : 0.f;
        float v4 = (s4 >= 0) ? __ldg(&g_xs[s4 * 8 + f]) : 0.f;
        float v5 = (s5 >= 0) ? __ldg(&g_xs[s5 * 8 + f]) : 0.f;
        float v6 = (s6 >= 0) ? __ldg(&g_xs[s6 * 8 + f]) : 0.f;
        float v7 = (s7 >= 0) ? __ldg(&g_xs[s7 * 8 + f]) : 0.f;
        acc += ((v0 + v1) + (v2 + v3)) + ((v4 + v5) + (v6 + v7));
    }
    acc += __shfl_down_sync(0xffffffffu, acc, 16);
    acc += __shfl_down_sync(0xffffffffu, acc, 8);
    float a0 = __shfl_sync(0xffffffffu, acc, 0);
    float a1 = __shfl_sync(0xffffffffu, acc, 1);
    float a2 = __shfl_sync(0xffffffffu, acc, 2);
    float a3 = __shfl_sync(0xffffffffu, acc, 3);
    float a4 = __shfl_sync(0xffffffffu, acc, 4);

    float dv = g_dinv[i];
    int k = lane;
    float z = a0 * __ldg(&W1[0 * HID + k]) + a1 * __ldg(&W1[1 * HID + k])
            + a2 * __ldg(&W1[2 * HID + k]) + a3 * __ldg(&W1[3 * HID + k])
            + a4 * __ldg(&W1[4 * HID + k]);
    float h = fmaxf(z * dv + __ldg(&b1[k]), 0.f);
    float p = h * __ldg(&W2[k]);
#pragma unroll
    for (int off = 16; off > 0; off >>= 1)
        p += __shfl_xor_sync(0xffffffffu, p, off);
    if (lane == 0) g_t2[i] = p * dv;
}

// --- layer-2 gather + sigmoid + output (8 nodes/warp, 4 lanes each) --------
// Lane r owns contiguous edges [8r, 8r+8) per window: 2x int4 index loads,
// then 8 predicated random t2 loads in flight.
__global__ void __launch_bounds__(256)
k_gather2(float* __restrict__ out, const float* __restrict__ b2, int n) {
    int t = blockIdx.x * blockDim.x + threadIdx.x;
    int i = t >> 2;                 // node (4 lanes per node)
    int r = t & 3;
    if (i >= n) return;
    int deg = g_cnt[i];
    if (deg > CAP) deg = CAP;
    const int* row = &g_bkt[i * CAP];

    float z = (r == 0) ? g_t2[i] : 0.f;    // self loop
    for (int base = 0; base < deg; base += 32) {
        int j0 = base + r * 8;
        const int4* rp = reinterpret_cast<const int4*>(&row[j0]);
        int4 ia = __ldg(rp);                // safe: g_bkt padded +32
        int4 ib = __ldg(rp + 1);
        float v0 = (j0 + 0 < deg) ? __ldg(&g_t2[ia.x]) : 0.f;  // 8 in flight
        float v1 = (j0 + 1 < deg) ? __ldg(&g_t2[ia.y]) : 0.f;
        float v2 = (j0 + 2 < deg) ? __ldg(&g_t2[ia.z]) : 0.f;
        float v3 = (j0 + 3 < deg) ? __ldg(&g_t2[ia.w]) : 0.f;
        float v4 = (j0 + 4 < deg) ? __ldg(&g_t2[ib.x]) : 0.f;
        float v5 = (j0 + 5 < deg) ? __ldg(&g_t2[ib.y]) : 0.f;
        float v6 = (j0 + 6 < deg) ? __ldg(&g_t2[ib.z]) : 0.f;
        float v7 = (j0 + 7 < deg) ? __ldg(&g_t2[ib.w]) : 0.f;
        z += ((v0 + v1) + (v2 + v3)) + ((v4 + v5) + (v6 + v7));
    }
    z += __shfl_xor_sync(0xffffffffu, z, 2);
    z += __shfl_xor_sync(0xffffffffu, z, 1);
    if (r == 0) {
        float v = z * g_dinv[i] + __ldg(&b2[0]);
        out[i] = 1.0f / (1.0f + expf(-v));
    }
}

extern "C" void kernel_launch(void* const* d_in, const int* in_sizes, int n_in,
                              void* d_out, int out_size) {
    const float* x  = (const float*)d_in[0];
    const int*   ei = (const int*)d_in[1];   // int32 (JAX x64 disabled)
    const float* W1 = (const float*)d_in[2];
    const float* b1 = (const float*)d_in[3];
    const float* W2 = (const float*)d_in[4];
    const float* b2 = (const float*)d_in[5];
    float* out = (float*)d_out;

    int n = in_sizes[0] / CIN;
    int e = in_sizes[1] / 2;
    const int* src = ei;
    const int* dst = ei + e;

    void* cnt_ptr = nullptr;
    cudaGetSymbolAddress(&cnt_ptr, g_cnt);
    cudaMemsetAsync(cnt_ptr, 0, (size_t)n * sizeof(int), 0);

    const int B = 256;
    int gridN = (n + B - 1) / B;
    int gridE = (e + B - 1) / B;
    long long tn32 = (long long)n * 32;
    long long tn4  = (long long)n * 4;
    int gridN32 = (int)((tn32 + B - 1) / B);
    int gridN4  = (int)((tn4  + B - 1) / B);

    k_fill   <<<gridE,   B>>>(src, dst, e);
    k_prep   <<<gridN,   B>>>(x, n);
    k_gather1<<<gridN32, B>>>(W1, b1, W2, n);
    k_gather2<<<gridN4,  B>>>(out, b2, n);
}